// round 16
// baseline (speedup 1.0000x reference)
#include <cuda_runtime.h>
#include <cuda_fp16.h>
#include <math_constants.h>
#include <cstdint>

#define BATCH 4
#define SEQ   2048
#define CH    1024
#define MROWS (BATCH * SEQ)   // 8192

// ---------------- scratch (device globals; allocation-free) ----------------
static __device__ __half g_xh[(size_t)MROWS * CH];            // x fp16
static __device__ __half g_wh[(size_t)3 * CH * CH];           // W fp16
static __device__ __half g_qh[(size_t)MROWS * CH];            // Q fp16
static __device__ __half g_kh[(size_t)MROWS * CH];            // K fp16
static __device__ __half g_vth[(size_t)BATCH * CH * SEQ];     // V^T fp16
static __device__ float  g_S [(size_t)BATCH * SEQ * SEQ];
static __device__ __half g_ph[(size_t)BATCH * SEQ * SEQ];     // P fp16

// ---------------- baseline-PTX helpers ----------------
__device__ __forceinline__ uint32_t su32(const void* p) {
    uint32_t a;
    asm("{ .reg .u64 t; cvta.to.shared.u64 t, %1; cvt.u32.u64 %0, t; }"
        : "=r"(a) : "l"(p));
    return a;
}
__device__ __forceinline__ void cpasync16(uint32_t dst, const void* src) {
    asm volatile("cp.async.cg.shared.global [%0], [%1], 16;"
                 :: "r"(dst), "l"(src) : "memory");
}
__device__ __forceinline__ void cpcommit() {
    asm volatile("cp.async.commit_group;" ::: "memory");
}
template<int N> __device__ __forceinline__ void cpwait() {
    asm volatile("cp.async.wait_group %0;" :: "n"(N) : "memory");
}
__device__ __forceinline__ void ldsm4(uint32_t* r, uint32_t addr) {
    asm volatile("ldmatrix.sync.aligned.m8n8.x4.shared.b16 {%0,%1,%2,%3}, [%4];"
                 : "=r"(r[0]), "=r"(r[1]), "=r"(r[2]), "=r"(r[3]) : "r"(addr));
}
__device__ __forceinline__ void mma16816(float* d, const uint32_t* a,
                                         const uint32_t* b) {
    asm volatile(
        "mma.sync.aligned.m16n8k16.row.col.f32.f16.f16.f32 "
        "{%0,%1,%2,%3},{%4,%5,%6,%7},{%8,%9},{%0,%1,%2,%3};"
        : "+f"(d[0]), "+f"(d[1]), "+f"(d[2]), "+f"(d[3])
        : "r"(a[0]), "r"(a[1]), "r"(a[2]), "r"(a[3]), "r"(b[0]), "r"(b[1]));
}
__device__ __forceinline__ uint32_t pk(__half a, __half b) {
    uint16_t x = reinterpret_cast<uint16_t&>(a);
    uint16_t y = reinterpret_cast<uint16_t&>(b);
    return (uint32_t)x | ((uint32_t)y << 16);
}

// ---------------- smem tile geometry ----------------
// Tiles: 128 rows x 32 halves (64 B data), padded stride 80 B.
// Stage: A 0, B 10240. Stage size 20480. 3 stages = 61440 B.
// Pipeline: lookahead 1, NSTAGE 3 => single barrier per chunk is safe:
// loads for kc+1 target stage (kc+1)%3 while the slowest warp computes
// kc-1 on stage (kc+2)%3 (disjoint).
#define T_STRIDE 80
#define OFF_B    10240
#define STAGE_SZ 20480
#define NSTAGE   3
#define SMEM_TOT (NSTAGE * STAGE_SZ)

__device__ __forceinline__ void tile_ld(uint32_t sdst, const __half* src,
                                        int ld, int tid) {
    #pragma unroll
    for (int it = 0; it < 2; it++) {
        int u = tid + it * 256;
        int r = u >> 2, q = u & 3;
        cpasync16(sdst + r * T_STRIDE + q * 16, src + (size_t)r * ld + q * 8);
    }
}
__device__ __forceinline__ void chunk_ld(uint32_t sbase, int st,
                                         const __half* A, const __half* B,
                                         int lda, int ldb, int k0, int tid) {
    const uint32_t s = sbase + st * STAGE_SZ;
    tile_ld(s,         A + k0, lda, tid);
    tile_ld(s + OFF_B, B + k0, ldb, tid);
    cpcommit();
}
// one 128x128 x k32 chunk; warp tile 32x64; single fp16 term.
__device__ __forceinline__ void compute_chunk(uint32_t sb, int wm0, int wn0,
                                              int lane, float acc[2][8][4]) {
    const int rowoff = lane & 15;
    const int koff   = (lane >> 4) * 16;
    #pragma unroll
    for (int ks = 0; ks < 2; ks++) {
        const int kb = ks * 32 + koff;
        uint32_t ah[2][4], bb[8][2];
        #pragma unroll
        for (int mi = 0; mi < 2; mi++)
            ldsm4(ah[mi], sb + (uint32_t)(wm0 + mi * 16 + rowoff) * T_STRIDE + kb);
        #pragma unroll
        for (int nf = 0; nf < 4; nf++) {
            uint32_t r4[4];
            ldsm4(r4, sb + OFF_B + (uint32_t)(wn0 + nf * 16 + rowoff) * T_STRIDE + kb);
            bb[nf*2][0] = r4[0]; bb[nf*2+1][0] = r4[1];
            bb[nf*2][1] = r4[2]; bb[nf*2+1][1] = r4[3];
        }
        #pragma unroll
        for (int mi = 0; mi < 2; mi++)
            #pragma unroll
            for (int ni = 0; ni < 8; ni++)
                mma16816(acc[mi][ni], ah[mi], bb[ni]);
    }
}
__device__ __forceinline__ void gemm_main(uint32_t sbase, int NK,
                                          const __half* A, const __half* B,
                                          int lda, int ldb, int tid,
                                          int wm0, int wn0, float acc[2][8][4]) {
    const int lane = tid & 31;
    chunk_ld(sbase, 0, A, B, lda, ldb, 0, tid);
    int st = 0;
    for (int kc = 0; kc < NK; kc++) {
        if (kc + 1 < NK) {
            int st1 = st + 1; if (st1 == NSTAGE) st1 = 0;
            chunk_ld(sbase, st1, A, B, lda, ldb, (kc + 1) * 32, tid);
            cpwait<1>();
        } else {
            cpwait<0>();
        }
        __syncthreads();
        compute_chunk(sbase + st * STAGE_SZ, wm0, wn0, lane, acc);
        // no trailing barrier: NSTAGE=3 guarantees the next chunk's loads
        // never touch the stage still being computed by straggler warps.
        if (++st == NSTAGE) st = 0;
    }
}

// ---------------------------------------------------------------------------
// Kernel 0: convert all fp32 inputs to fp16 (single launch).
// ---------------------------------------------------------------------------
__global__ __launch_bounds__(256) void split_kernel(
    const float* __restrict__ x,  const float* __restrict__ Wq,
    const float* __restrict__ Wk, const float* __restrict__ Wv) {
    const size_t NX = (size_t)MROWS * CH;
    const size_t NW = (size_t)CH * CH;
    size_t i = ((size_t)blockIdx.x * 256 + threadIdx.x) * 4;

    const float* src;
    __half* dst;
    size_t off, loc;
    if (i < NX)             { src = x;  dst = g_xh; off = i;      loc = i; }
    else if (i < NX + NW)   { src = Wq; dst = g_wh; off = i - NX; loc = off; }
    else if (i < NX + 2*NW) { src = Wk; dst = g_wh; off = i - NX; loc = off - NW; }
    else if (i < NX + 3*NW) { src = Wv; dst = g_wh; off = i - NX; loc = off - 2*NW; }
    else return;

    float4 v = *(const float4*)(src + loc);
    *(uint32_t*)(dst + off)     = pk(__float2half(v.x), __float2half(v.y));
    *(uint32_t*)(dst + off + 2) = pk(__float2half(v.z), __float2half(v.w));
}

// ---------------------------------------------------------------------------
// Kernel 1: QKV = xh * Wh. grid (8*3, 64). Q,K fp16; V transposed fp16.
// ---------------------------------------------------------------------------
__global__ __launch_bounds__(256, 2) void qkv_kernel() {
    extern __shared__ char sm[];
    const int tid = threadIdx.x, wid = tid >> 5, lane = tid & 31;
    const int mat = blockIdx.x >> 3;
    const int n0  = (blockIdx.x & 7) * 128;
    const int m0  = blockIdx.y * 128;
    const int wm0 = (wid & 3) * 32, wn0 = (wid >> 2) * 64;
    const uint32_t sbase = su32(sm);

    const __half* A = g_xh + (size_t)m0 * CH;
    const __half* B = g_wh + (size_t)mat * CH * CH + (size_t)n0 * CH;

    float acc[2][8][4] = {};
    gemm_main(sbase, CH / 32, A, B, CH, CH, tid, wm0, wn0, acc);

    const int qrow = lane >> 2, qcol = (lane & 3) * 2;
    if (mat < 2) {
        __half* Hd = mat ? g_kh : g_qh;
        #pragma unroll
        for (int mi = 0; mi < 2; mi++)
            #pragma unroll
            for (int ni = 0; ni < 8; ni++)
                #pragma unroll
                for (int h = 0; h < 2; h++) {
                    int row = m0 + wm0 + mi*16 + qrow + h*8;
                    int col = n0 + wn0 + ni*8 + qcol;
                    *(uint32_t*)&Hd[(size_t)row * CH + col] =
                        pk(__float2half(acc[mi][ni][h*2]),
                           __float2half(acc[mi][ni][h*2+1]));
                }
    } else {
        #pragma unroll
        for (int mi = 0; mi < 2; mi++)
            #pragma unroll
            for (int ni = 0; ni < 8; ni++)
                #pragma unroll
                for (int h = 0; h < 2; h++) {
                    int row = m0 + wm0 + mi*16 + qrow + h*8;   // token
                    int b = row >> 11, t = row & (SEQ - 1);
                    int col = n0 + wn0 + ni*8 + qcol;          // channel
                    #pragma unroll
                    for (int j = 0; j < 2; j++) {
                        size_t idx = ((size_t)b * CH + col + j) * SEQ + t;
                        g_vth[idx] = __float2half(acc[mi][ni][h*2+j]);
                    }
                }
    }
}

// ---------------------------------------------------------------------------
// Kernel 2: scores = (1/32) * Qh * Kh^T. Skip strictly-upper tiles.
// ---------------------------------------------------------------------------
__global__ __launch_bounds__(256, 2) void scores_kernel() {
    if (blockIdx.x > blockIdx.y) return;
    extern __shared__ char sm[];
    const int tid = threadIdx.x, wid = tid >> 5, lane = tid & 31;
    const int b  = blockIdx.z;
    const int s0 = blockIdx.x * 128;
    const int t0 = blockIdx.y * 128;
    const int wm0 = (wid & 3) * 32, wn0 = (wid >> 2) * 64;
    const uint32_t sbase = su32(sm);

    const size_t ar = (size_t)(b * SEQ + t0) * CH;
    const size_t br = (size_t)(b * SEQ + s0) * CH;

    float acc[2][8][4] = {};
    gemm_main(sbase, CH / 32, g_qh + ar, g_kh + br, CH, CH, tid, wm0, wn0, acc);

    const int qrow = lane >> 2, qcol = (lane & 3) * 2;
    const float scl = 0.03125f;
    #pragma unroll
    for (int mi = 0; mi < 2; mi++)
        #pragma unroll
        for (int ni = 0; ni < 8; ni++)
            #pragma unroll
            for (int h = 0; h < 2; h++) {
                int t = t0 + wm0 + mi*16 + qrow + h*8;
                int s = s0 + wn0 + ni*8 + qcol;
                *(float2*)&g_S[((size_t)b * SEQ + t) * SEQ + s] =
                    make_float2(acc[mi][ni][h*2] * scl, acc[mi][ni][h*2+1] * scl);
            }
}

// ---------------------------------------------------------------------------
// Kernel 3: row softmax; writes P fp16, zeros to 128-tile boundary.
// ---------------------------------------------------------------------------
__global__ __launch_bounds__(256) void softmax_kernel() {
    const int t = blockIdx.x;
    const int b = blockIdx.y;
    const size_t rowb = ((size_t)b * SEQ + t) * SEQ;
    const float* Srow = g_S + rowb;
    const int tid = threadIdx.x;
    const int len = ((t >> 7) + 1) << 7;

    float v[8];
    float m = -CUDART_INF_F;
    #pragma unroll
    for (int i = 0; i < 8; i++) {
        int s = tid + i * 256;
        v[i] = (s <= t) ? Srow[s] : -CUDART_INF_F;
        m = fmaxf(m, v[i]);
    }
    #pragma unroll
    for (int o = 16; o; o >>= 1) m = fmaxf(m, __shfl_xor_sync(~0u, m, o));
    __shared__ float smax[8], ssum[8];
    if ((tid & 31) == 0) smax[tid >> 5] = m;
    __syncthreads();
    m = smax[0];
    #pragma unroll
    for (int i = 1; i < 8; i++) m = fmaxf(m, smax[i]);

    float s = 0.f;
    #pragma unroll
    for (int i = 0; i < 8; i++) { v[i] = expf(v[i] - m); s += v[i]; }
    #pragma unroll
    for (int o = 16; o; o >>= 1) s += __shfl_xor_sync(~0u, s, o);
    if ((tid & 31) == 0) ssum[tid >> 5] = s;
    __syncthreads();
    s = 0.f;
    #pragma unroll
    for (int i = 0; i < 8; i++) s += ssum[i];
    const float inv = 1.0f / s;

    #pragma unroll
    for (int i = 0; i < 8; i++) {
        int sc = tid + i * 256;
        if (sc < len) g_ph[rowb + sc] = __float2half(v[i] * inv);
    }
}

// ---------------------------------------------------------------------------
// Kernel 4: O = Ph * Vh^T. K clipped at t0+128.
// ---------------------------------------------------------------------------
__global__ __launch_bounds__(256, 2) void pv_kernel(float* __restrict__ out) {
    extern __shared__ char sm[];
    const int tid = threadIdx.x, wid = tid >> 5, lane = tid & 31;
    const int b  = blockIdx.z;
    const int c0 = blockIdx.x * 128;
    const int t0 = blockIdx.y * 128;
    const int wm0 = (wid & 3) * 32, wn0 = (wid >> 2) * 64;
    const uint32_t sbase = su32(sm);

    const __half* A = g_ph  + ((size_t)b * SEQ + t0) * SEQ;
    const __half* B = g_vth + ((size_t)b * CH + c0) * SEQ;

    float acc[2][8][4] = {};
    gemm_main(sbase, (t0 + 128) / 32, A, B, SEQ, SEQ, tid, wm0, wn0, acc);

    const int qrow = lane >> 2, qcol = (lane & 3) * 2;
    #pragma unroll
    for (int mi = 0; mi < 2; mi++)
        #pragma unroll
        for (int ni = 0; ni < 8; ni++)
            #pragma unroll
            for (int h = 0; h < 2; h++) {
                int t = t0 + wm0 + mi*16 + qrow + h*8;
                int c = c0 + wn0 + ni*8 + qcol;
                *(float2*)&out[((size_t)b * SEQ + t) * CH + c] =
                    make_float2(acc[mi][ni][h*2], acc[mi][ni][h*2+1]);
            }
}

// ---------------------------------------------------------------------------
extern "C" void kernel_launch(void* const* d_in, const int* in_sizes, int n_in,
                              void* d_out, int out_size)
{
    const float* x  = (const float*)d_in[0];
    const float* Wq = (const float*)d_in[1];
    const float* Wk = (const float*)d_in[2];
    const float* Wv = (const float*)d_in[3];
    float* out = (float*)d_out;

    cudaFuncSetAttribute(qkv_kernel,
                         cudaFuncAttributeMaxDynamicSharedMemorySize, SMEM_TOT);
    cudaFuncSetAttribute(scores_kernel,
                         cudaFuncAttributeMaxDynamicSharedMemorySize, SMEM_TOT);
    cudaFuncSetAttribute(pv_kernel,
                         cudaFuncAttributeMaxDynamicSharedMemorySize, SMEM_TOT);

    const size_t n_split = (size_t)MROWS * CH + 3 * (size_t)CH * CH;
    split_kernel<<<(unsigned)(n_split / 1024), 256>>>(x, Wq, Wk, Wv);

    qkv_kernel<<<dim3(8 * 3, MROWS / 128), 256, SMEM_TOT>>>();
    scores_kernel<<<dim3(SEQ / 128, SEQ / 128, BATCH), 256, SMEM_TOT>>>();
    softmax_kernel<<<dim3(SEQ, BATCH), 256>>>();
    pv_kernel<<<dim3(CH / 128, SEQ / 128, BATCH), 256, SMEM_TOT>>>(out);
}

// round 17
// speedup vs baseline: 1.3697x; 1.3697x over previous
#include <cuda_runtime.h>
#include <cuda_fp16.h>
#include <math_constants.h>
#include <cstdint>

#define BATCH 4
#define SEQ   2048
#define CH    1024
#define MROWS (BATCH * SEQ)   // 8192

// ---------------- scratch (device globals; allocation-free) ----------------
static __device__ __half g_xh[(size_t)MROWS * CH];            // x fp16
static __device__ __half g_wh[(size_t)3 * CH * CH];           // W fp16
static __device__ __half g_qh[(size_t)MROWS * CH];            // Q fp16
static __device__ __half g_kh[(size_t)MROWS * CH];            // K fp16
static __device__ __half g_vth[(size_t)BATCH * CH * SEQ];     // V^T fp16
static __device__ __half g_S [(size_t)BATCH * SEQ * SEQ];     // scaled logits fp16
static __device__ __half g_ph[(size_t)BATCH * SEQ * SEQ];     // P fp16

// ---------------- baseline-PTX helpers ----------------
__device__ __forceinline__ uint32_t su32(const void* p) {
    uint32_t a;
    asm("{ .reg .u64 t; cvta.to.shared.u64 t, %1; cvt.u32.u64 %0, t; }"
        : "=r"(a) : "l"(p));
    return a;
}
__device__ __forceinline__ void cpasync16(uint32_t dst, const void* src) {
    asm volatile("cp.async.cg.shared.global [%0], [%1], 16;"
                 :: "r"(dst), "l"(src) : "memory");
}
__device__ __forceinline__ void cpcommit() {
    asm volatile("cp.async.commit_group;" ::: "memory");
}
template<int N> __device__ __forceinline__ void cpwait() {
    asm volatile("cp.async.wait_group %0;" :: "n"(N) : "memory");
}
__device__ __forceinline__ void ldsm4(uint32_t* r, uint32_t addr) {
    asm volatile("ldmatrix.sync.aligned.m8n8.x4.shared.b16 {%0,%1,%2,%3}, [%4];"
                 : "=r"(r[0]), "=r"(r[1]), "=r"(r[2]), "=r"(r[3]) : "r"(addr));
}
__device__ __forceinline__ void mma16816(float* d, const uint32_t* a,
                                         const uint32_t* b) {
    asm volatile(
        "mma.sync.aligned.m16n8k16.row.col.f32.f16.f16.f32 "
        "{%0,%1,%2,%3},{%4,%5,%6,%7},{%8,%9},{%0,%1,%2,%3};"
        : "+f"(d[0]), "+f"(d[1]), "+f"(d[2]), "+f"(d[3])
        : "r"(a[0]), "r"(a[1]), "r"(a[2]), "r"(a[3]), "r"(b[0]), "r"(b[1]));
}
__device__ __forceinline__ uint32_t pk(__half a, __half b) {
    uint16_t x = reinterpret_cast<uint16_t&>(a);
    uint16_t y = reinterpret_cast<uint16_t&>(b);
    return (uint32_t)x | ((uint32_t)y << 16);
}

// ---------------- smem tile geometry (R15 champion: 2 stages, 2 barriers) ---
#define T_STRIDE 80
#define OFF_B    10240
#define STAGE_SZ 20480
#define SMEM_TOT (2 * STAGE_SZ)

__device__ __forceinline__ void tile_ld(uint32_t sdst, const __half* src,
                                        int ld, int tid) {
    #pragma unroll
    for (int it = 0; it < 2; it++) {
        int u = tid + it * 256;
        int r = u >> 2, q = u & 3;
        cpasync16(sdst + r * T_STRIDE + q * 16, src + (size_t)r * ld + q * 8);
    }
}
__device__ __forceinline__ void chunk_ld(uint32_t sbase, int st,
                                         const __half* A, const __half* B,
                                         int lda, int ldb, int k0, int tid) {
    const uint32_t s = sbase + st * STAGE_SZ;
    tile_ld(s,         A + k0, lda, tid);
    tile_ld(s + OFF_B, B + k0, ldb, tid);
    cpcommit();
}
// one 128x128 x k32 chunk; warp tile 32x64; single fp16 term.
__device__ __forceinline__ void compute_chunk(uint32_t sb, int wm0, int wn0,
                                              int lane, float acc[2][8][4]) {
    const int rowoff = lane & 15;
    const int koff   = (lane >> 4) * 16;
    #pragma unroll
    for (int ks = 0; ks < 2; ks++) {
        const int kb = ks * 32 + koff;
        uint32_t ah[2][4], bb[8][2];
        #pragma unroll
        for (int mi = 0; mi < 2; mi++)
            ldsm4(ah[mi], sb + (uint32_t)(wm0 + mi * 16 + rowoff) * T_STRIDE + kb);
        #pragma unroll
        for (int nf = 0; nf < 4; nf++) {
            uint32_t r4[4];
            ldsm4(r4, sb + OFF_B + (uint32_t)(wn0 + nf * 16 + rowoff) * T_STRIDE + kb);
            bb[nf*2][0] = r4[0]; bb[nf*2+1][0] = r4[1];
            bb[nf*2][1] = r4[2]; bb[nf*2+1][1] = r4[3];
        }
        #pragma unroll
        for (int mi = 0; mi < 2; mi++)
            #pragma unroll
            for (int ni = 0; ni < 8; ni++)
                mma16816(acc[mi][ni], ah[mi], bb[ni]);
    }
}
__device__ __forceinline__ void gemm_main(uint32_t sbase, int NK,
                                          const __half* A, const __half* B,
                                          int lda, int ldb, int tid,
                                          int wm0, int wn0, float acc[2][8][4]) {
    const int lane = tid & 31;
    chunk_ld(sbase, 0, A, B, lda, ldb, 0, tid);
    for (int kc = 0; kc < NK; kc++) {
        if (kc + 1 < NK) {
            chunk_ld(sbase, (kc + 1) & 1, A, B, lda, ldb, (kc + 1) * 32, tid);
            cpwait<1>();
        } else {
            cpwait<0>();
        }
        __syncthreads();
        compute_chunk(sbase + (kc & 1) * STAGE_SZ, wm0, wn0, lane, acc);
        __syncthreads();
    }
}

// ---------------------------------------------------------------------------
// Kernel 0: convert all fp32 inputs to fp16 (single launch).
// ---------------------------------------------------------------------------
__global__ __launch_bounds__(256) void split_kernel(
    const float* __restrict__ x,  const float* __restrict__ Wq,
    const float* __restrict__ Wk, const float* __restrict__ Wv) {
    const size_t NX = (size_t)MROWS * CH;
    const size_t NW = (size_t)CH * CH;
    size_t i = ((size_t)blockIdx.x * 256 + threadIdx.x) * 4;

    const float* src;
    __half* dst;
    size_t off, loc;
    if (i < NX)             { src = x;  dst = g_xh; off = i;      loc = i; }
    else if (i < NX + NW)   { src = Wq; dst = g_wh; off = i - NX; loc = off; }
    else if (i < NX + 2*NW) { src = Wk; dst = g_wh; off = i - NX; loc = off - NW; }
    else if (i < NX + 3*NW) { src = Wv; dst = g_wh; off = i - NX; loc = off - 2*NW; }
    else return;

    float4 v = *(const float4*)(src + loc);
    *(uint32_t*)(dst + off)     = pk(__float2half(v.x), __float2half(v.y));
    *(uint32_t*)(dst + off + 2) = pk(__float2half(v.z), __float2half(v.w));
}

// ---------------------------------------------------------------------------
// Kernel 1: QKV = xh * Wh. grid (8*3, 64). Q,K fp16; V transposed fp16.
// ---------------------------------------------------------------------------
__global__ __launch_bounds__(256, 2) void qkv_kernel() {
    extern __shared__ char sm[];
    const int tid = threadIdx.x, wid = tid >> 5, lane = tid & 31;
    const int mat = blockIdx.x >> 3;
    const int n0  = (blockIdx.x & 7) * 128;
    const int m0  = blockIdx.y * 128;
    const int wm0 = (wid & 3) * 32, wn0 = (wid >> 2) * 64;
    const uint32_t sbase = su32(sm);

    const __half* A = g_xh + (size_t)m0 * CH;
    const __half* B = g_wh + (size_t)mat * CH * CH + (size_t)n0 * CH;

    float acc[2][8][4] = {};
    gemm_main(sbase, CH / 32, A, B, CH, CH, tid, wm0, wn0, acc);

    const int qrow = lane >> 2, qcol = (lane & 3) * 2;
    if (mat < 2) {
        __half* Hd = mat ? g_kh : g_qh;
        #pragma unroll
        for (int mi = 0; mi < 2; mi++)
            #pragma unroll
            for (int ni = 0; ni < 8; ni++)
                #pragma unroll
                for (int h = 0; h < 2; h++) {
                    int row = m0 + wm0 + mi*16 + qrow + h*8;
                    int col = n0 + wn0 + ni*8 + qcol;
                    *(uint32_t*)&Hd[(size_t)row * CH + col] =
                        pk(__float2half(acc[mi][ni][h*2]),
                           __float2half(acc[mi][ni][h*2+1]));
                }
    } else {
        #pragma unroll
        for (int mi = 0; mi < 2; mi++)
            #pragma unroll
            for (int ni = 0; ni < 8; ni++)
                #pragma unroll
                for (int h = 0; h < 2; h++) {
                    int row = m0 + wm0 + mi*16 + qrow + h*8;   // token
                    int b = row >> 11, t = row & (SEQ - 1);
                    int col = n0 + wn0 + ni*8 + qcol;          // channel
                    #pragma unroll
                    for (int j = 0; j < 2; j++) {
                        size_t idx = ((size_t)b * CH + col + j) * SEQ + t;
                        g_vth[idx] = __float2half(acc[mi][ni][h*2+j]);
                    }
                }
    }
}

// ---------------------------------------------------------------------------
// Kernel 2: S(fp16) = (1/32) * Qh * Kh^T. Skip strictly-upper tiles.
// ---------------------------------------------------------------------------
__global__ __launch_bounds__(256, 2) void scores_kernel() {
    if (blockIdx.x > blockIdx.y) return;
    extern __shared__ char sm[];
    const int tid = threadIdx.x, wid = tid >> 5, lane = tid & 31;
    const int b  = blockIdx.z;
    const int s0 = blockIdx.x * 128;
    const int t0 = blockIdx.y * 128;
    const int wm0 = (wid & 3) * 32, wn0 = (wid >> 2) * 64;
    const uint32_t sbase = su32(sm);

    const size_t ar = (size_t)(b * SEQ + t0) * CH;
    const size_t br = (size_t)(b * SEQ + s0) * CH;

    float acc[2][8][4] = {};
    gemm_main(sbase, CH / 32, g_qh + ar, g_kh + br, CH, CH, tid, wm0, wn0, acc);

    const int qrow = lane >> 2, qcol = (lane & 3) * 2;
    const float scl = 0.03125f;
    #pragma unroll
    for (int mi = 0; mi < 2; mi++)
        #pragma unroll
        for (int ni = 0; ni < 8; ni++)
            #pragma unroll
            for (int h = 0; h < 2; h++) {
                int t = t0 + wm0 + mi*16 + qrow + h*8;
                int s = s0 + wn0 + ni*8 + qcol;
                *(uint32_t*)&g_S[((size_t)b * SEQ + t) * SEQ + s] =
                    pk(__float2half(acc[mi][ni][h*2] * scl),
                       __float2half(acc[mi][ni][h*2+1] * scl));
            }
}

// ---------------------------------------------------------------------------
// Kernel 3: row softmax over fp16 S; writes P fp16, zeros to tile boundary.
// ---------------------------------------------------------------------------
__global__ __launch_bounds__(256) void softmax_kernel() {
    const int t = blockIdx.x;
    const int b = blockIdx.y;
    const size_t rowb = ((size_t)b * SEQ + t) * SEQ;
    const __half* Srow = g_S + rowb;
    const int tid = threadIdx.x;
    const int len = ((t >> 7) + 1) << 7;

    float v[8];
    float m = -CUDART_INF_F;
    #pragma unroll
    for (int i = 0; i < 8; i++) {
        int s = tid + i * 256;
        v[i] = (s <= t) ? __half2float(Srow[s]) : -CUDART_INF_F;
        m = fmaxf(m, v[i]);
    }
    #pragma unroll
    for (int o = 16; o; o >>= 1) m = fmaxf(m, __shfl_xor_sync(~0u, m, o));
    __shared__ float smax[8], ssum[8];
    if ((tid & 31) == 0) smax[tid >> 5] = m;
    __syncthreads();
    m = smax[0];
    #pragma unroll
    for (int i = 1; i < 8; i++) m = fmaxf(m, smax[i]);

    float s = 0.f;
    #pragma unroll
    for (int i = 0; i < 8; i++) { v[i] = expf(v[i] - m); s += v[i]; }
    #pragma unroll
    for (int o = 16; o; o >>= 1) s += __shfl_xor_sync(~0u, s, o);
    if ((tid & 31) == 0) ssum[tid >> 5] = s;
    __syncthreads();
    s = 0.f;
    #pragma unroll
    for (int i = 0; i < 8; i++) s += ssum[i];
    const float inv = 1.0f / s;

    #pragma unroll
    for (int i = 0; i < 8; i++) {
        int sc = tid + i * 256;
        if (sc < len) g_ph[rowb + sc] = __float2half(v[i] * inv);
    }
}

// ---------------------------------------------------------------------------
// Kernel 4: O = Ph * Vh^T. K clipped at t0+128.
// ---------------------------------------------------------------------------
__global__ __launch_bounds__(256, 2) void pv_kernel(float* __restrict__ out) {
    extern __shared__ char sm[];
    const int tid = threadIdx.x, wid = tid >> 5, lane = tid & 31;
    const int b  = blockIdx.z;
    const int c0 = blockIdx.x * 128;
    const int t0 = blockIdx.y * 128;
    const int wm0 = (wid & 3) * 32, wn0 = (wid >> 2) * 64;
    const uint32_t sbase = su32(sm);

    const __half* A = g_ph  + ((size_t)b * SEQ + t0) * SEQ;
    const __half* B = g_vth + ((size_t)b * CH + c0) * SEQ;

    float acc[2][8][4] = {};
    gemm_main(sbase, (t0 + 128) / 32, A, B, SEQ, SEQ, tid, wm0, wn0, acc);

    const int qrow = lane >> 2, qcol = (lane & 3) * 2;
    #pragma unroll
    for (int mi = 0; mi < 2; mi++)
        #pragma unroll
        for (int ni = 0; ni < 8; ni++)
            #pragma unroll
            for (int h = 0; h < 2; h++) {
                int t = t0 + wm0 + mi*16 + qrow + h*8;
                int c = c0 + wn0 + ni*8 + qcol;
                *(float2*)&out[((size_t)b * SEQ + t) * CH + c] =
                    make_float2(acc[mi][ni][h*2], acc[mi][ni][h*2+1]);
            }
}

// ---------------------------------------------------------------------------
extern "C" void kernel_launch(void* const* d_in, const int* in_sizes, int n_in,
                              void* d_out, int out_size)
{
    const float* x  = (const float*)d_in[0];
    const float* Wq = (const float*)d_in[1];
    const float* Wk = (const float*)d_in[2];
    const float* Wv = (const float*)d_in[3];
    float* out = (float*)d_out;

    cudaFuncSetAttribute(qkv_kernel,
                         cudaFuncAttributeMaxDynamicSharedMemorySize, SMEM_TOT);
    cudaFuncSetAttribute(scores_kernel,
                         cudaFuncAttributeMaxDynamicSharedMemorySize, SMEM_TOT);
    cudaFuncSetAttribute(pv_kernel,
                         cudaFuncAttributeMaxDynamicSharedMemorySize, SMEM_TOT);

    const size_t n_split = (size_t)MROWS * CH + 3 * (size_t)CH * CH;
    split_kernel<<<(unsigned)(n_split / 1024), 256>>>(x, Wq, Wk, Wv);

    qkv_kernel<<<dim3(8 * 3, MROWS / 128), 256, SMEM_TOT>>>();
    scores_kernel<<<dim3(SEQ / 128, SEQ / 128, BATCH), 256, SMEM_TOT>>>();
    softmax_kernel<<<dim3(SEQ, BATCH), 256>>>();
    pv_kernel<<<dim3(CH / 128, SEQ / 128, BATCH), 256, SMEM_TOT>>>(out);
}